// round 5
// baseline (speedup 1.0000x reference)
#include <cuda_runtime.h>
#include <math.h>

// NUFFTLayerMultiChannel: B=16, N=1024, M=2049, two output channels.
// Pipeline: spread (windowed Gaussian) -> half-spectrum DFT -> real even
// k-multiplier (L/2pi * deconv^2 * mult_c) -> inverse DFT (conj-symmetric
// fold, factor 2) -> windowed Gaussian inverse interpolation -> /M.

#define MM 2049
#define BB 16
#define NN 1024
#define KH 1025   // k = 0..1024 (half spectrum incl. Nyquist)

static __device__ float  g_xg[MM];          // XGRID (fp32, via exact f64 path)
static __device__ float2 g_tw[MM];          // (cos, sin)(2*pi*r/M)
static __device__ float  g_w1[KH];          // (L/2pi)*deconv^2*m1
static __device__ float  g_w2[KH];          // (L/2pi)*deconv^2*m2
static __device__ float  g_gsum[BB * MM];   // gridded density
static __device__ float4 g_A[BB * KH];      // (W1*F.re, W1*F.im, W2*F.re, W2*F.im)
static __device__ float  g_ir[BB * 2 * MM]; // irfft (B, 2, M)

// ---------------------------------------------------------------------------
// K0: constant tables (xgrid, twiddles, combined k-space multipliers)
// ---------------------------------------------------------------------------
__global__ void k0_tables(const float* __restrict__ s0, const float* __restrict__ a0,
                          const float* __restrict__ s1, const float* __restrict__ a1) {
    int i = blockIdx.x * blockDim.x + threadIdx.x;
    const double PI = 3.14159265358979323846;
    if (i < MM) {
        // np.linspace(0,10,2050)[:-1]: arr[i] = i * (10/2049); XGRID = 2*pi*arr/10
        double step = 10.0 / 2049.0;
        g_xg[i] = (float)((2.0 * PI * ((double)i * step)) / 10.0);
        double sv, cv;
        sincospi(2.0 * (double)i / (double)MM, &sv, &cv);
        g_tw[i] = make_float2((float)cv, (float)sv);
    }
    if (i < KH) {
        const double tau = 2.821e-5;
        double k2  = (double)i * (double)i;           // KGRID^2 (symmetric in k)
        double dec = sqrt(PI / tau) * exp(k2 * tau);  // deconv
        double base = (10.0 / (2.0 * PI)) * dec * dec; // (L/2pi) * deconv^2
        double sh0 = (double)s0[0], am0 = (double)a0[0];
        double sh1 = (double)s1[0], am1 = (double)a1[0];
        double m1 = -am0 * 4.0 * PI / (k2 + 25.0 * sh0 * sh0);
        double dn = k2 + 25.0 * sh1 * sh1;
        double m2 = am1 * 4.0 * PI / (dn * dn);
        g_w1[i] = (float)(base * m1);
        g_w2[i] = (float)(base * m2);
    }
}

// ---------------------------------------------------------------------------
// K1: Gaussian spreading, gather form (deterministic; no atomics).
// One thread per (b, m); loop all n in order (matches dense reference sum —
// terms outside the fp32 support are exactly 0 and change nothing).
// ---------------------------------------------------------------------------
__global__ void k1_spread(const float* __restrict__ x) {
    __shared__ float ps[NN];
    int b = blockIdx.y;
    const float cf = (float)(2.0 * 3.14159265358979323846 / 10.0);
    for (int n = threadIdx.x; n < NN; n += blockDim.x)
        ps[n] = x[b * NN + n] * cf;          // x * (2*pi/L), rounded once (as ref)
    __syncthreads();
    int m = blockIdx.x * blockDim.x + threadIdx.x;
    if (m >= MM) return;
    const float xg = g_xg[m];
    const float ft = (float)(4.0 * 2.821e-5);
    float acc = 0.0f;
    for (int n = 0; n < NN; ++n) {
        float d = ps[n] - xg;
        float q = d * d;
        // q >= 0.0118 => expf underflows to exactly 0 in fp32
        if (q < 0.0118f) acc += expf((-q) / ft);
    }
    g_gsum[b * MM + m] = acc;
}

// ---------------------------------------------------------------------------
// K2: half-spectrum DFT of gsum + apply combined multipliers.
// F[b,k] = sum_m gsum[b,m] * e^{-2pi i k m / M}, k = 0..1024.
// Twiddle index r = (k*m) mod M via incremental add-and-wrap.
// Chunked accumulation (256) keeps per-bin rounding in the FFT error class.
// ---------------------------------------------------------------------------
__global__ void k2_dft(void) {
    __shared__ float  gs[MM];
    __shared__ float2 tws[MM];
    int b = blockIdx.y;
    for (int i = threadIdx.x; i < MM; i += blockDim.x) {
        gs[i]  = g_gsum[b * MM + i];
        tws[i] = g_tw[i];
    }
    __syncthreads();
    int k = blockIdx.x * blockDim.x + threadIdx.x;
    if (k >= KH) return;
    float re = 0.0f, im = 0.0f;
    int r = 0;
    for (int m0 = 0; m0 < MM; m0 += 256) {
        float cre = 0.0f, cim = 0.0f;
        int mend = min(m0 + 256, MM);
#pragma unroll 4
        for (int m = m0; m < mend; ++m) {
            float g  = gs[m];
            float2 t = tws[r];
            cre = fmaf(g,  t.x, cre);
            cim = fmaf(g, -t.y, cim);
            r += k; if (r >= MM) r -= MM;   // k <= 1024 < M: one subtract suffices
        }
        re += cre; im += cim;
    }
    float w1 = g_w1[k], w2 = g_w2[k];
    g_A[b * KH + k] = make_float4(w1 * re, w1 * im, w2 * re, w2 * im);
}

// ---------------------------------------------------------------------------
// K4: inverse DFT to the mesh for both channels.
// irfft[b,c,j] = (1/M) * ( A_c[0].re + 2 * sum_{k=1}^{1024}
//                          (ReA*cos(2pi jk/M) - ImA*sin(2pi jk/M)) )
// (conjugate-symmetric fold; multiplier is real & even so irfft is real).
// ---------------------------------------------------------------------------
__global__ void k4_idft(void) {
    __shared__ float4 As[KH];
    __shared__ float2 tws[MM];
    int b = blockIdx.y;
    for (int i = threadIdx.x; i < MM; i += blockDim.x) tws[i] = g_tw[i];
    for (int i = threadIdx.x; i < KH; i += blockDim.x) As[i] = g_A[b * KH + i];
    __syncthreads();
    int j = blockIdx.x * blockDim.x + threadIdx.x;
    if (j >= MM) return;
    float s1 = 0.0f, s2 = 0.0f;
    int r = j;                                // r for k=1 is j
    for (int k0 = 1; k0 < KH; k0 += 256) {
        float c1 = 0.0f, c2 = 0.0f;
        int kend = min(k0 + 256, KH);
#pragma unroll 4
        for (int kk = k0; kk < kend; ++kk) {
            float4 a = As[kk];
            float2 t = tws[r];
            c1 = fmaf(a.x,  t.x, c1);
            c1 = fmaf(-a.y, t.y, c1);
            c2 = fmaf(a.z,  t.x, c2);
            c2 = fmaf(-a.w, t.y, c2);
            r += j; if (r >= MM) r -= MM;     // j <= 2048, r < 2*M: one subtract ok
        }
        s1 += c1; s2 += c2;
    }
    const float invM = (float)(1.0 / 2049.0);
    float4 a0 = As[0];
    g_ir[(b * 2 + 0) * MM + j] = (a0.x + 2.0f * s1) * invM;
    g_ir[(b * 2 + 1) * MM + j] = (a0.z + 2.0f * s2) * invM;
}

// ---------------------------------------------------------------------------
// K5: inverse interpolation back to the points (windowed; identical fp32 g).
// fmm[b,n,c] = ( sum_j irfft[b,c,j] * g[b,n,j] ) / M
// ---------------------------------------------------------------------------
__global__ void k5_gather(const float* __restrict__ x, float* __restrict__ out) {
    int idx = blockIdx.x * blockDim.x + threadIdx.x;   // b*NN + n
    if (idx >= BB * NN) return;
    int b = idx >> 10;
    const float cf = (float)(2.0 * 3.14159265358979323846 / 10.0);
    float p  = x[idx] * cf;
    float jf = p * (float)(2049.0 / (2.0 * 3.14159265358979323846));
    int lo = (int)jf - 37; if (lo < 0) lo = 0;
    int hi = (int)jf + 37; if (hi > MM - 1) hi = MM - 1;
    const float ft = (float)(4.0 * 2.821e-5);
    const float* ir1 = g_ir + (b * 2 + 0) * MM;
    const float* ir2 = g_ir + (b * 2 + 1) * MM;
    float a1 = 0.0f, a2 = 0.0f;
    for (int j = lo; j <= hi; ++j) {
        float d = p - g_xg[j];
        float q = d * d;
        if (q < 0.0118f) {
            float g = expf((-q) / ft);
            a1 = fmaf(ir1[j], g, a1);
            a2 = fmaf(ir2[j], g, a2);
        }
    }
    out[idx * 2 + 0] = a1 / 2049.0f;
    out[idx * 2 + 1] = a2 / 2049.0f;
}

// ---------------------------------------------------------------------------
extern "C" void kernel_launch(void* const* d_in, const int* in_sizes, int n_in,
                              void* d_out, int out_size) {
    const float* x  = (const float*)d_in[0];
    const float* s0 = (const float*)d_in[1];
    const float* a0 = (const float*)d_in[2];
    const float* s1 = (const float*)d_in[3];
    const float* a1 = (const float*)d_in[4];
    float* out = (float*)d_out;

    k0_tables<<<(MM + 255) / 256, 256>>>(s0, a0, s1, a1);
    k1_spread<<<dim3((MM + 255) / 256, BB), 256>>>(x);
    k2_dft  <<<dim3((KH + 255) / 256, BB), 256>>>();
    k4_idft <<<dim3((MM + 127) / 128, BB), 128>>>();
    k5_gather<<<(BB * NN + 255) / 256, 256>>>(x, out);
}

// round 10
// speedup vs baseline: 2.1073x; 2.1073x over previous
#include <cuda_runtime.h>
#include <math.h>

// NUFFTLayerMultiChannel: B=16, N=1024, M=2049, two output channels.
// Spread (sorted + windowed Gaussian) -> half-spectrum DFT with real-input
// fold -> real even k-multiplier -> inverse DFT with output fold -> windowed
// Gaussian interpolation -> /M.
// Transforms: 4 independent in-register rotation streams per thread (ILP to
// cover the FMA dependency chain at ~1 warp/SMSP occupancy), exact-table
// resync every 128 steps.

#define MM 2049
#define BB 16
#define NN 1024
#define KH 1025   // k (or j) = 0..1024

static __device__ float  g_xg[MM];          // XGRID (fp32, via exact f64 path)
static __device__ float2 g_tw[MM];          // (cos, sin)(2*pi*r/M)
static __device__ float  g_w1[KH];          // (L/2pi)*deconv^2*m1
static __device__ float  g_w2[KH];          // (L/2pi)*deconv^2*m2
static __device__ float  g_ps[BB * NN];     // sorted p = x*(2pi/L) per batch
static __device__ float  g_gsum[BB * MM];   // gridded density
static __device__ float4 g_A[BB * KH];      // (W1*F.re, W1*F.im, W2*F.re, W2*F.im)
static __device__ float  g_ir[BB * 2 * MM]; // irfft (B, 2, M)

// ---------------------------------------------------------------------------
// K0: constant tables
// ---------------------------------------------------------------------------
__global__ void k0_tables(const float* __restrict__ s0, const float* __restrict__ a0,
                          const float* __restrict__ s1, const float* __restrict__ a1) {
    int i = blockIdx.x * blockDim.x + threadIdx.x;
    const double PI = 3.14159265358979323846;
    if (i < MM) {
        double step = 10.0 / 2049.0;
        g_xg[i] = (float)((2.0 * PI * ((double)i * step)) / 10.0);
        double sv, cv;
        sincospi(2.0 * (double)i / (double)MM, &sv, &cv);
        g_tw[i] = make_float2((float)cv, (float)sv);
    }
    if (i < KH) {
        const double tau = 2.821e-5;
        double k2  = (double)i * (double)i;
        double dec = sqrt(PI / tau) * exp(k2 * tau);
        double base = (10.0 / (2.0 * PI)) * dec * dec;
        double sh0 = (double)s0[0], am0 = (double)a0[0];
        double sh1 = (double)s1[0], am1 = (double)a1[0];
        double m1 = -am0 * 4.0 * PI / (k2 + 25.0 * sh0 * sh0);
        double dn = k2 + 25.0 * sh1 * sh1;
        double m2 = am1 * 4.0 * PI / (dn * dn);
        g_w1[i] = (float)(base * m1);
        g_w2[i] = (float)(base * m2);
    }
}

// ---------------------------------------------------------------------------
// K1a: per-batch bitonic sort of p = x*(2pi/L). Data-independent compare
// network => deterministic output for identical inputs.
// ---------------------------------------------------------------------------
__global__ void k1a_sort(const float* __restrict__ x) {
    __shared__ float ps[NN];
    int b = blockIdx.x;
    const float cf = (float)(2.0 * 3.14159265358979323846 / 10.0);
    for (int n = threadIdx.x; n < NN; n += blockDim.x)
        ps[n] = __ldg(&x[b * NN + n]) * cf;
    __syncthreads();
    for (int k = 2; k <= NN; k <<= 1) {
        for (int j = k >> 1; j > 0; j >>= 1) {
            for (int i = threadIdx.x; i < NN; i += blockDim.x) {
                int ixj = i ^ j;
                if (ixj > i) {
                    float a = ps[i], c = ps[ixj];
                    bool up = ((i & k) == 0);
                    if (up ? (a > c) : (a < c)) { ps[i] = c; ps[ixj] = a; }
                }
            }
            __syncthreads();
        }
    }
    for (int n = threadIdx.x; n < NN; n += blockDim.x)
        g_ps[b * NN + n] = ps[n];
}

// ---------------------------------------------------------------------------
// K1b: windowed Gaussian spreading from the sorted point list.
// expf(-q/ft) is exactly +0.0f for q >= 0.0118 (fp32 underflow), so the
// window [xg-0.1087, xg+0.1087] covers every nonzero term of the dense sum.
// ---------------------------------------------------------------------------
__global__ void k1b_spread(void) {
    __shared__ float ps[NN];
    int b = blockIdx.y;
    for (int n = threadIdx.x; n < NN; n += blockDim.x)
        ps[n] = g_ps[b * NN + n];
    __syncthreads();
    int m = blockIdx.x * blockDim.x + threadIdx.x;
    if (m >= MM) return;
    const float xg = g_xg[m];
    const float wlo = xg - 0.1087f, whi = xg + 0.1087f;
    int l = 0, r = NN;                       // first index with ps >= wlo
    while (l < r) { int mid = (l + r) >> 1; if (ps[mid] < wlo) l = mid + 1; else r = mid; }
    const float ft = (float)(4.0 * 2.821e-5);
    float acc = 0.0f;
    for (int n = l; n < NN; ++n) {
        float p = ps[n];
        if (p > whi) break;
        float d = p - xg;
        float q = d * d;
        if (q < 0.0118f) acc += expf((-q) / ft);
    }
    g_gsum[b * MM + m] = acc;
}

// ---------------------------------------------------------------------------
// K2: half-spectrum DFT with real-input fold + combined multipliers.
// Re F[k] = g0 + sum_{m=1}^{1024} (g[m]+g[M-m]) cos(2pi k m/M)
// Im F[k] = -   sum_{m=1}^{1024} (g[m]-g[M-m]) sin(2pi k m/M)
// 4 rotation streams (m-ranges of 256), resync every 128.
// ---------------------------------------------------------------------------
__global__ void k2_dft(void) {
    __shared__ float2 tws[MM];
    __shared__ float2 gpm[KH];
    int b = blockIdx.y;
    const float* __restrict__ gs = g_gsum + b * MM;
    for (int i = threadIdx.x; i < MM; i += blockDim.x) tws[i] = g_tw[i];
    for (int i = threadIdx.x; i < KH; i += blockDim.x) {
        if (i == 0) gpm[0] = make_float2(gs[0], 0.0f);
        else        gpm[i] = make_float2(gs[i] + gs[MM - i], gs[i] - gs[MM - i]);
    }
    __syncthreads();
    int k = blockIdx.x * blockDim.x + threadIdx.x;
    if (k >= KH) return;
    const float2 tk = tws[k];
    const int step = (k * 128) % MM;
    int r[4];  float c[4], s[4], re[4], im[4];
#pragma unroll
    for (int q = 0; q < 4; ++q) {
        r[q] = (int)(((long long)k * (1 + 256 * q)) % MM);
        re[q] = 0.0f; im[q] = 0.0f;
    }
    for (int seg = 0; seg < 2; ++seg) {
#pragma unroll
        for (int q = 0; q < 4; ++q) { float2 t = tws[r[q]]; c[q] = t.x; s[q] = t.y; }
#pragma unroll 4
        for (int it = 0; it < 128; ++it) {
#pragma unroll
            for (int q = 0; q < 4; ++q) {
                int m = 1 + 256 * q + 128 * seg + it;
                float2 gv = gpm[m];
                re[q] = fmaf(gv.x, c[q], re[q]);
                im[q] = fmaf(gv.y, s[q], im[q]);
                float cn = fmaf(c[q], tk.x, -(s[q] * tk.y));
                float sn = fmaf(s[q], tk.x,  (c[q] * tk.y));
                c[q] = cn; s[q] = sn;
            }
        }
#pragma unroll
        for (int q = 0; q < 4; ++q) { r[q] += step; if (r[q] >= MM) r[q] -= MM; }
    }
    float reT = gpm[0].x + ((re[0] + re[1]) + (re[2] + re[3]));
    float imT = -((im[0] + im[1]) + (im[2] + im[3]));
    float w1 = g_w1[k], w2 = g_w2[k];
    g_A[b * KH + k] = make_float4(w1 * reT, w1 * imT, w2 * reT, w2 * imT);
}

// ---------------------------------------------------------------------------
// K4: inverse DFT with output fold (one thread -> mesh points j and M-j).
// irfft[j]   = (A0 + 2*(U - V))/M,  irfft[M-j] = (A0 + 2*(U + V))/M
// U = sum_k ReA cos(2pi j k/M),  V = sum_k ImA sin(2pi j k/M)
// 4 rotation streams (k-ranges of 256), resync every 128.
// ---------------------------------------------------------------------------
__global__ void k4_idft(void) {
    __shared__ float2 tws[MM];
    __shared__ float4 As[KH];
    int b = blockIdx.y;
    for (int i = threadIdx.x; i < MM; i += blockDim.x) tws[i] = g_tw[i];
    for (int i = threadIdx.x; i < KH; i += blockDim.x) As[i] = g_A[b * KH + i];
    __syncthreads();
    int j = blockIdx.x * blockDim.x + threadIdx.x;
    if (j >= KH) return;
    const float2 tj = tws[j];
    const int step = (j * 128) % MM;
    int r[4];  float c[4], s[4], u1[4], v1[4], u2[4], v2[4];
#pragma unroll
    for (int q = 0; q < 4; ++q) {
        r[q] = (int)(((long long)j * (1 + 256 * q)) % MM);
        u1[q] = v1[q] = u2[q] = v2[q] = 0.0f;
    }
    for (int seg = 0; seg < 2; ++seg) {
#pragma unroll
        for (int q = 0; q < 4; ++q) { float2 t = tws[r[q]]; c[q] = t.x; s[q] = t.y; }
#pragma unroll 2
        for (int it = 0; it < 128; ++it) {
#pragma unroll
            for (int q = 0; q < 4; ++q) {
                int k = 1 + 256 * q + 128 * seg + it;
                float4 a = As[k];
                u1[q] = fmaf(a.x, c[q], u1[q]);
                v1[q] = fmaf(a.y, s[q], v1[q]);
                u2[q] = fmaf(a.z, c[q], u2[q]);
                v2[q] = fmaf(a.w, s[q], v2[q]);
                float cn = fmaf(c[q], tj.x, -(s[q] * tj.y));
                float sn = fmaf(s[q], tj.x,  (c[q] * tj.y));
                c[q] = cn; s[q] = sn;
            }
        }
#pragma unroll
        for (int q = 0; q < 4; ++q) { r[q] += step; if (r[q] >= MM) r[q] -= MM; }
    }
    float U1 = (u1[0] + u1[1]) + (u1[2] + u1[3]);
    float V1 = (v1[0] + v1[1]) + (v1[2] + v1[3]);
    float U2 = (u2[0] + u2[1]) + (u2[2] + u2[3]);
    float V2 = (v2[0] + v2[1]) + (v2[2] + v2[3]);
    const float invM = (float)(1.0 / 2049.0);
    float4 a0 = As[0];
    float* __restrict__ ir1 = g_ir + (b * 2 + 0) * MM;
    float* __restrict__ ir2 = g_ir + (b * 2 + 1) * MM;
    ir1[j] = (a0.x + 2.0f * (U1 - V1)) * invM;
    ir2[j] = (a0.z + 2.0f * (U2 - V2)) * invM;
    if (j > 0) {
        ir1[MM - j] = (a0.x + 2.0f * (U1 + V1)) * invM;
        ir2[MM - j] = (a0.z + 2.0f * (U2 + V2)) * invM;
    }
}

// ---------------------------------------------------------------------------
// K5: inverse interpolation back to the points (reference-exact fp32 g)
// ---------------------------------------------------------------------------
__global__ void k5_gather(const float* __restrict__ x, float* __restrict__ out) {
    int idx = blockIdx.x * blockDim.x + threadIdx.x;   // b*NN + n
    if (idx >= BB * NN) return;
    int b = idx >> 10;
    const float cf = (float)(2.0 * 3.14159265358979323846 / 10.0);
    float p  = __ldg(&x[idx]) * cf;
    float jf = p * (float)(2049.0 / (2.0 * 3.14159265358979323846));
    int lo = (int)jf - 37; if (lo < 0) lo = 0;
    int hi = (int)jf + 37; if (hi > MM - 1) hi = MM - 1;
    const float ft = (float)(4.0 * 2.821e-5);
    const float* __restrict__ ir1 = g_ir + (b * 2 + 0) * MM;
    const float* __restrict__ ir2 = g_ir + (b * 2 + 1) * MM;
    float a1 = 0.0f, a2 = 0.0f;
    for (int j = lo; j <= hi; ++j) {
        float d = p - g_xg[j];
        float q = d * d;
        if (q < 0.0118f) {
            float g = expf((-q) / ft);
            a1 = fmaf(__ldg(&ir1[j]), g, a1);
            a2 = fmaf(__ldg(&ir2[j]), g, a2);
        }
    }
    out[idx * 2 + 0] = a1 / 2049.0f;
    out[idx * 2 + 1] = a2 / 2049.0f;
}

// ---------------------------------------------------------------------------
extern "C" void kernel_launch(void* const* d_in, const int* in_sizes, int n_in,
                              void* d_out, int out_size) {
    const float* x  = (const float*)d_in[0];
    const float* s0 = (const float*)d_in[1];
    const float* a0 = (const float*)d_in[2];
    const float* s1 = (const float*)d_in[3];
    const float* a1 = (const float*)d_in[4];
    float* out = (float*)d_out;

    k0_tables<<<(MM + 255) / 256, 256>>>(s0, a0, s1, a1);
    k1a_sort <<<BB, 512>>>(x);
    k1b_spread<<<dim3((MM + 255) / 256, BB), 256>>>();
    k2_dft   <<<dim3((KH + 127) / 128, BB), 128>>>();
    k4_idft  <<<dim3((KH + 127) / 128, BB), 128>>>();
    k5_gather<<<(BB * NN + 255) / 256, 256>>>(x, out);
}

// round 11
// speedup vs baseline: 2.4307x; 1.1535x over previous
#include <cuda_runtime.h>
#include <math.h>

// NUFFTLayerMultiChannel: B=16, N=1024, M=2049, two output channels.
// Spread (sorted + windowed Gaussian) -> half-spectrum DFT with real-input
// fold -> real even k-multiplier -> inverse DFT with output fold -> windowed
// Gaussian interpolation -> /M.
// Transforms: 512-thread blocks; 4 thread-slices per output bin each sum a
// 256-wide quarter of the reduction (2 in-register rotation streams of 128),
// partials combined via smem. ~4 warps/SMSP hides the FMA rotation chain.

#define MM 2049
#define BB 16
#define NN 1024
#define KH 1025   // k (or j) = 0..1024

static __device__ float  g_xg[MM];          // XGRID (fp32, via exact f64 path)
static __device__ float2 g_tw[MM];          // (cos, sin)(2*pi*r/M)
static __device__ float  g_w1[KH];          // (L/2pi)*deconv^2*m1
static __device__ float  g_w2[KH];          // (L/2pi)*deconv^2*m2
static __device__ float  g_ps[BB * NN];     // sorted p = x*(2pi/L) per batch
static __device__ float  g_gsum[BB * MM];   // gridded density
static __device__ float4 g_A[BB * KH];      // (W1*F.re, W1*F.im, W2*F.re, W2*F.im)
static __device__ float  g_ir[BB * 2 * MM]; // irfft (B, 2, M)

// ---------------------------------------------------------------------------
// K1a: per-batch bitonic sort of p = x*(2pi/L)  +  table slice (fused k0).
// Block b sorts batch b and computes table entries [b*129, b*129+129).
// ---------------------------------------------------------------------------
__global__ void k1a_sort(const float* __restrict__ x,
                         const float* __restrict__ s0, const float* __restrict__ a0,
                         const float* __restrict__ s1, const float* __restrict__ a1) {
    __shared__ float ps[NN];
    int b = blockIdx.x;
    const double PI = 3.14159265358979323846;
    // ---- table slice (independent of the sort; no sync needed) ----
    int tbase = b * 129;
    for (int t = threadIdx.x; t < 129; t += blockDim.x) {
        int i = tbase + t;
        if (i < MM) {
            double step = 10.0 / 2049.0;
            g_xg[i] = (float)((2.0 * PI * ((double)i * step)) / 10.0);
            double sv, cv;
            sincospi(2.0 * (double)i / (double)MM, &sv, &cv);
            g_tw[i] = make_float2((float)cv, (float)sv);
        }
        if (i < KH) {
            const double tau = 2.821e-5;
            double k2  = (double)i * (double)i;
            double dec = sqrt(PI / tau) * exp(k2 * tau);
            double base = (10.0 / (2.0 * PI)) * dec * dec;
            double sh0 = (double)s0[0], am0 = (double)a0[0];
            double sh1 = (double)s1[0], am1 = (double)a1[0];
            double m1 = -am0 * 4.0 * PI / (k2 + 25.0 * sh0 * sh0);
            double dn = k2 + 25.0 * sh1 * sh1;
            double m2 = am1 * 4.0 * PI / (dn * dn);
            g_w1[i] = (float)(base * m1);
            g_w2[i] = (float)(base * m2);
        }
    }
    // ---- bitonic sort (data-independent network => deterministic) ----
    const float cf = (float)(2.0 * 3.14159265358979323846 / 10.0);
    for (int n = threadIdx.x; n < NN; n += blockDim.x)
        ps[n] = __ldg(&x[b * NN + n]) * cf;
    __syncthreads();
    for (int k = 2; k <= NN; k <<= 1) {
        for (int j = k >> 1; j > 0; j >>= 1) {
            for (int i = threadIdx.x; i < NN; i += blockDim.x) {
                int ixj = i ^ j;
                if (ixj > i) {
                    float a = ps[i], c = ps[ixj];
                    bool up = ((i & k) == 0);
                    if (up ? (a > c) : (a < c)) { ps[i] = c; ps[ixj] = a; }
                }
            }
            __syncthreads();
        }
    }
    for (int n = threadIdx.x; n < NN; n += blockDim.x)
        g_ps[b * NN + n] = ps[n];
}

// ---------------------------------------------------------------------------
// K1b: windowed Gaussian spreading from the sorted point list.
// expf(-q/ft) is exactly +0.0f for q >= 0.0118 (fp32 underflow), so the
// window [xg-0.1087, xg+0.1087] covers every nonzero term of the dense sum.
// ---------------------------------------------------------------------------
__global__ void k1b_spread(void) {
    __shared__ float ps[NN];
    int b = blockIdx.y;
    for (int n = threadIdx.x; n < NN; n += blockDim.x)
        ps[n] = g_ps[b * NN + n];
    __syncthreads();
    int m = blockIdx.x * blockDim.x + threadIdx.x;
    if (m >= MM) return;
    const float xg = g_xg[m];
    const float wlo = xg - 0.1087f, whi = xg + 0.1087f;
    int l = 0, r = NN;                       // first index with ps >= wlo
    while (l < r) { int mid = (l + r) >> 1; if (ps[mid] < wlo) l = mid + 1; else r = mid; }
    const float ft = (float)(4.0 * 2.821e-5);
    float acc = 0.0f;
    for (int n = l; n < NN; ++n) {
        float p = ps[n];
        if (p > whi) break;
        float d = p - xg;
        float q = d * d;
        if (q < 0.0118f) acc += expf((-q) / ft);
    }
    g_gsum[b * MM + m] = acc;
}

// ---------------------------------------------------------------------------
// K2: half-spectrum DFT with real-input fold + combined multipliers.
// Re F[k] = g0 + sum_{m=1}^{1024} (g[m]+g[M-m]) cos(2pi k m/M)
// Im F[k] = -   sum_{m=1}^{1024} (g[m]-g[M-m]) sin(2pi k m/M)
// 512 threads = 4 slices x 128 k-bins; slice q sums m in [1+256q, 256+256q]
// via 2 rotation streams of 128; partials combined in smem.
// ---------------------------------------------------------------------------
__global__ void k2_dft(void) {
    __shared__ float2 tws[MM];
    __shared__ float2 gpm[KH];
    __shared__ float2 part[4][128];
    int b = blockIdx.y;
    const float* __restrict__ gs = g_gsum + b * MM;
    for (int i = threadIdx.x; i < MM; i += blockDim.x) tws[i] = g_tw[i];
    for (int i = threadIdx.x; i < KH; i += blockDim.x) {
        if (i == 0) gpm[0] = make_float2(gs[0], 0.0f);
        else        gpm[i] = make_float2(gs[i] + gs[MM - i], gs[i] - gs[MM - i]);
    }
    __syncthreads();
    int kl    = threadIdx.x & 127;
    int slice = threadIdx.x >> 7;
    int k = blockIdx.x * 128 + kl;
    float reT = 0.0f, imT = 0.0f;
    if (k < KH) {
        const float2 tk = tws[k];
        int mbase = 1 + 256 * slice;
        int r0 = (int)(((long long)k * mbase) % MM);
        int r1 = (int)(((long long)k * (mbase + 128)) % MM);
        float2 t0 = tws[r0], t1 = tws[r1];
        float c0 = t0.x, s0 = t0.y, c1 = t1.x, s1 = t1.y;
        float re0 = 0.0f, im0 = 0.0f, re1 = 0.0f, im1 = 0.0f;
#pragma unroll 4
        for (int it = 0; it < 128; ++it) {
            float2 gv0 = gpm[mbase + it];
            float2 gv1 = gpm[mbase + 128 + it];
            re0 = fmaf(gv0.x, c0, re0);
            im0 = fmaf(gv0.y, s0, im0);
            re1 = fmaf(gv1.x, c1, re1);
            im1 = fmaf(gv1.y, s1, im1);
            float cn0 = fmaf(c0, tk.x, -(s0 * tk.y));
            float sn0 = fmaf(s0, tk.x,  (c0 * tk.y));
            float cn1 = fmaf(c1, tk.x, -(s1 * tk.y));
            float sn1 = fmaf(s1, tk.x,  (c1 * tk.y));
            c0 = cn0; s0 = sn0; c1 = cn1; s1 = sn1;
        }
        reT = re0 + re1; imT = im0 + im1;
    }
    part[slice][kl] = make_float2(reT, imT);
    __syncthreads();
    if (slice == 0 && k < KH) {
        float re = gpm[0].x + ((part[0][kl].x + part[1][kl].x) + (part[2][kl].x + part[3][kl].x));
        float im = -((part[0][kl].y + part[1][kl].y) + (part[2][kl].y + part[3][kl].y));
        float w1 = g_w1[k], w2 = g_w2[k];
        g_A[b * KH + k] = make_float4(w1 * re, w1 * im, w2 * re, w2 * im);
    }
}

// ---------------------------------------------------------------------------
// K4: inverse DFT with output fold (one bin -> mesh points j and M-j).
// irfft[j]   = (A0 + 2*(U - V))/M,  irfft[M-j] = (A0 + 2*(U + V))/M
// U = sum_k ReA cos(2pi j k/M),  V = sum_k ImA sin(2pi j k/M)
// 512 threads = 4 slices x 128 j-bins; slice q sums k in [1+256q, 256+256q]
// via 2 rotation streams of 128; partials combined in smem.
// ---------------------------------------------------------------------------
__global__ void k4_idft(void) {
    __shared__ float2 tws[MM];
    __shared__ float4 As[KH];
    __shared__ float4 part[4][128];   // (U1, V1, U2, V2) partials
    int b = blockIdx.y;
    for (int i = threadIdx.x; i < MM; i += blockDim.x) tws[i] = g_tw[i];
    for (int i = threadIdx.x; i < KH; i += blockDim.x) As[i] = g_A[b * KH + i];
    __syncthreads();
    int jl    = threadIdx.x & 127;
    int slice = threadIdx.x >> 7;
    int j = blockIdx.x * 128 + jl;
    float U1 = 0.0f, V1 = 0.0f, U2 = 0.0f, V2 = 0.0f;
    if (j < KH) {
        const float2 tj = tws[j];
        int kbase = 1 + 256 * slice;
        int r0 = (int)(((long long)j * kbase) % MM);
        int r1 = (int)(((long long)j * (kbase + 128)) % MM);
        float2 t0 = tws[r0], t1 = tws[r1];
        float c0 = t0.x, s0 = t0.y, c1 = t1.x, s1 = t1.y;
        float u10 = 0.0f, v10 = 0.0f, u20 = 0.0f, v20 = 0.0f;
        float u11 = 0.0f, v11 = 0.0f, u21 = 0.0f, v21 = 0.0f;
#pragma unroll 2
        for (int it = 0; it < 128; ++it) {
            float4 a0v = As[kbase + it];
            float4 a1v = As[kbase + 128 + it];
            u10 = fmaf(a0v.x, c0, u10);
            v10 = fmaf(a0v.y, s0, v10);
            u20 = fmaf(a0v.z, c0, u20);
            v20 = fmaf(a0v.w, s0, v20);
            u11 = fmaf(a1v.x, c1, u11);
            v11 = fmaf(a1v.y, s1, v11);
            u21 = fmaf(a1v.z, c1, u21);
            v21 = fmaf(a1v.w, s1, v21);
            float cn0 = fmaf(c0, tj.x, -(s0 * tj.y));
            float sn0 = fmaf(s0, tj.x,  (c0 * tj.y));
            float cn1 = fmaf(c1, tj.x, -(s1 * tj.y));
            float sn1 = fmaf(s1, tj.x,  (c1 * tj.y));
            c0 = cn0; s0 = sn0; c1 = cn1; s1 = sn1;
        }
        U1 = u10 + u11; V1 = v10 + v11;
        U2 = u20 + u21; V2 = v20 + v21;
    }
    part[slice][jl] = make_float4(U1, V1, U2, V2);
    __syncthreads();
    if (slice == 0 && j < KH) {
        float4 p0 = part[0][jl], p1 = part[1][jl], p2 = part[2][jl], p3 = part[3][jl];
        float U1t = (p0.x + p1.x) + (p2.x + p3.x);
        float V1t = (p0.y + p1.y) + (p2.y + p3.y);
        float U2t = (p0.z + p1.z) + (p2.z + p3.z);
        float V2t = (p0.w + p1.w) + (p2.w + p3.w);
        const float invM = (float)(1.0 / 2049.0);
        float4 a0 = As[0];
        float* __restrict__ ir1 = g_ir + (b * 2 + 0) * MM;
        float* __restrict__ ir2 = g_ir + (b * 2 + 1) * MM;
        ir1[j] = (a0.x + 2.0f * (U1t - V1t)) * invM;
        ir2[j] = (a0.z + 2.0f * (U2t - V2t)) * invM;
        if (j > 0) {
            ir1[MM - j] = (a0.x + 2.0f * (U1t + V1t)) * invM;
            ir2[MM - j] = (a0.z + 2.0f * (U2t + V2t)) * invM;
        }
    }
}

// ---------------------------------------------------------------------------
// K5: inverse interpolation back to the points (reference-exact fp32 g)
// ---------------------------------------------------------------------------
__global__ void k5_gather(const float* __restrict__ x, float* __restrict__ out) {
    int idx = blockIdx.x * blockDim.x + threadIdx.x;   // b*NN + n
    if (idx >= BB * NN) return;
    int b = idx >> 10;
    const float cf = (float)(2.0 * 3.14159265358979323846 / 10.0);
    float p  = __ldg(&x[idx]) * cf;
    float jf = p * (float)(2049.0 / (2.0 * 3.14159265358979323846));
    int lo = (int)jf - 37; if (lo < 0) lo = 0;
    int hi = (int)jf + 37; if (hi > MM - 1) hi = MM - 1;
    const float ft = (float)(4.0 * 2.821e-5);
    const float* __restrict__ ir1 = g_ir + (b * 2 + 0) * MM;
    const float* __restrict__ ir2 = g_ir + (b * 2 + 1) * MM;
    float a1 = 0.0f, a2 = 0.0f;
    for (int j = lo; j <= hi; ++j) {
        float d = p - g_xg[j];
        float q = d * d;
        if (q < 0.0118f) {
            float g = expf((-q) / ft);
            a1 = fmaf(__ldg(&ir1[j]), g, a1);
            a2 = fmaf(__ldg(&ir2[j]), g, a2);
        }
    }
    out[idx * 2 + 0] = a1 / 2049.0f;
    out[idx * 2 + 1] = a2 / 2049.0f;
}

// ---------------------------------------------------------------------------
extern "C" void kernel_launch(void* const* d_in, const int* in_sizes, int n_in,
                              void* d_out, int out_size) {
    const float* x  = (const float*)d_in[0];
    const float* s0 = (const float*)d_in[1];
    const float* a0 = (const float*)d_in[2];
    const float* s1 = (const float*)d_in[3];
    const float* a1 = (const float*)d_in[4];
    float* out = (float*)d_out;

    k1a_sort <<<BB, 512>>>(x, s0, a0, s1, a1);
    k1b_spread<<<dim3((MM + 255) / 256, BB), 256>>>();
    k2_dft   <<<dim3((KH + 127) / 128, BB), 512>>>();
    k4_idft  <<<dim3((KH + 127) / 128, BB), 512>>>();
    k5_gather<<<(BB * NN + 255) / 256, 256>>>(x, out);
}